// round 7
// baseline (speedup 1.0000x reference)
#include <cuda_runtime.h>
#include <cuda_bf16.h>

#define RED_BLOCKS 1184          // 148 SMs * 8
#define RED_THREADS 256

__device__ float g_partials[RED_BLOCKS];
__device__ unsigned int g_ticket;   // zero-initialized; atomicInc wraps back to 0

__global__ void __launch_bounds__(RED_THREADS, 8)
qsum_fused_kernel(const float* __restrict__ phi,
                  const float* __restrict__ w,
                  int n, int nblocks,
                  float add_const, float inv_m,
                  float* __restrict__ out)
{
    const int n4 = n >> 2;
    const float4* __restrict__ p4 = reinterpret_cast<const float4*>(phi);
    const float4* __restrict__ w4 = reinterpret_cast<const float4*>(w);

    const int stride = gridDim.x * blockDim.x;

    float acc = 0.0f;

    for (int i = blockIdx.x * blockDim.x + threadIdx.x; i < n4; i += stride) {
        // prefetch 2 iterations ahead into L2 (no reg result, no scoreboard)
        int pf = i + 2 * stride;
        if (pf < n4) {
            asm volatile("prefetch.global.L2 [%0];" :: "l"(p4 + pf));
            asm volatile("prefetch.global.L2 [%0];" :: "l"(w4 + pf));
        }
        float4 p = p4[i];
        float4 q = w4[i];
        acc += __cosf(p.x * q.x);
        acc += __cosf(p.y * q.y);
        acc += __cosf(p.z * q.z);
        acc += __cosf(p.w * q.w);
    }

    // scalar tail (n % 4 elements)
    int tail = n - (n4 << 2);
    int gtid = blockIdx.x * blockDim.x + threadIdx.x;
    if (gtid < tail) {
        int idx = (n4 << 2) + gtid;
        acc += __cosf(phi[idx] * w[idx]);
    }

    // warp reduce
    #pragma unroll
    for (int off = 16; off > 0; off >>= 1)
        acc += __shfl_down_sync(0xFFFFFFFFu, acc, off);

    __shared__ float s_warp[RED_THREADS / 32];
    int lane = threadIdx.x & 31;
    int wid  = threadIdx.x >> 5;
    if (lane == 0) s_warp[wid] = acc;
    __syncthreads();

    __shared__ bool s_last;
    if (threadIdx.x == 0) {
        float v = 0.0f;
        #pragma unroll
        for (int k = 0; k < RED_THREADS / 32; k++) v += s_warp[k];
        g_partials[blockIdx.x] = v;
        __threadfence();
        // atomicInc wraps to 0 when old == nblocks-1 -> counter self-resets
        unsigned int t = atomicInc(&g_ticket, (unsigned int)(nblocks - 1));
        s_last = (t == (unsigned int)(nblocks - 1));
    }
    __syncthreads();

    if (s_last) {
        // last block: deterministic fixed-order reduction of partials in double
        __shared__ double s_red[RED_THREADS / 32];
        double v = 0.0;
        for (int k = threadIdx.x; k < nblocks; k += RED_THREADS)
            v += (double)g_partials[k];
        #pragma unroll
        for (int off = 16; off > 0; off >>= 1)
            v += __shfl_down_sync(0xFFFFFFFFu, v, off);
        if (lane == 0) s_red[wid] = v;
        __syncthreads();
        if (wid == 0) {
            double x = (lane < RED_THREADS / 32) ? s_red[lane] : 0.0;
            #pragma unroll
            for (int off = 4; off > 0; off >>= 1)
                x += __shfl_down_sync(0xFFFFFFFFu, x, off);
            if (lane == 0)
                out[0] = (float)((x + (double)add_const) * (double)inv_m);
        }
    }
}

extern "C" void kernel_launch(void* const* d_in, const int* in_sizes, int n_in,
                              void* d_out, int out_size)
{
    const float* phi = (const float*)d_in[0];
    const float* w   = (const float*)d_in[1];
    float* out = (float*)d_out;
    int n = in_sizes[0];

    long long M = 1;
    while (M < (long long)n) M <<= 1;
    float add_const = (float)(M - (long long)n);
    float inv_m = (float)(1.0 / (double)M);

    int blocks = RED_BLOCKS;
    long long work4 = (n >> 2);
    if (work4 < (long long)blocks * RED_THREADS) {
        blocks = (int)((work4 + RED_THREADS - 1) / RED_THREADS);
        if (blocks < 1) blocks = 1;
    }

    qsum_fused_kernel<<<blocks, RED_THREADS>>>(phi, w, n, blocks,
                                               add_const, inv_m, out);
}

// round 10
// speedup vs baseline: 1.0045x; 1.0045x over previous
#include <cuda_runtime.h>
#include <cuda_bf16.h>
#include <cstdint>

#define NBLOCKS  1024
#define THREADS  256
#define NSTAGES  3

__device__ float g_partials[NBLOCKS];
__device__ unsigned int g_ticket;   // zero-init; atomicInc wraps back to 0

__device__ __forceinline__ void cp16(uint32_t dst, const void* src) {
    asm volatile("cp.async.cg.shared.global [%0], [%1], 16;"
                 :: "r"(dst), "l"(src) : "memory");
}
__device__ __forceinline__ void cp_commit() {
    asm volatile("cp.async.commit_group;" ::: "memory");
}
template <int N> __device__ __forceinline__ void cp_wait() {
    asm volatile("cp.async.wait_group %0;" :: "n"(N) : "memory");
}

__global__ void __launch_bounds__(THREADS, 8)
qsum_cpasync_kernel(const float* __restrict__ phi,
                    const float* __restrict__ w,
                    int n, float add_const, float inv_m,
                    float* __restrict__ out)
{
    // per-thread private slots: buf[stage][arr][tid], 16B each (24 KB total)
    __shared__ float4 buf[NSTAGES][2][THREADS];

    const int tid  = threadIdx.x;
    const int gtid = blockIdx.x * THREADS + tid;
    const int G    = NBLOCKS * THREADS;          // total threads
    const int n4   = n >> 2;                     // float4 count per array
    const int iters = n4 / G;                    // full pipelined iterations

    const float4* __restrict__ p4 = reinterpret_cast<const float4*>(phi);
    const float4* __restrict__ w4 = reinterpret_cast<const float4*>(w);

    uint32_t sp[NSTAGES], sq[NSTAGES];
    #pragma unroll
    for (int s = 0; s < NSTAGES; s++) {
        sp[s] = (uint32_t)__cvta_generic_to_shared(&buf[s][0][tid]);
        sq[s] = (uint32_t)__cvta_generic_to_shared(&buf[s][1][tid]);
    }

    float acc = 0.0f;

    if (iters >= NSTAGES) {
        // prologue: one commit group per iteration
        #pragma unroll
        for (int k = 0; k < NSTAGES; k++) {
            int idx = gtid + k * G;
            cp16(sp[k], p4 + idx);
            cp16(sq[k], w4 + idx);
            cp_commit();
        }

        // unroll by NSTAGES so s is compile-time constant in each body:
        // slot addresses stay in registers (no local-memory indexed access)
        #pragma unroll 3
        for (int i = 0; i < iters; i++) {
            int s = i % NSTAGES;
            cp_wait<NSTAGES - 1>();              // group i complete
            float4 p = buf[s][0][tid];
            float4 q = buf[s][1][tid];

            // refill same slot for iteration i+NSTAGES (always commit a
            // group so the pending count stays exact)
            int nxt = i + NSTAGES;
            if (nxt < iters) {
                int idx = gtid + nxt * G;
                cp16(sp[s], p4 + idx);
                cp16(sq[s], w4 + idx);
            }
            cp_commit();

            acc += __cosf(p.x * q.x);
            acc += __cosf(p.y * q.y);
            acc += __cosf(p.z * q.z);
            acc += __cosf(p.w * q.w);
        }
        cp_wait<0>();
    }

    // leftover float4s (n4 % G, plus the iters<NSTAGES case) via plain LDG
    int start = (iters >= NSTAGES) ? iters * G : 0;
    for (int i = start + gtid; i < n4; i += G) {
        float4 p = p4[i];
        float4 q = w4[i];
        acc += __cosf(p.x * q.x);
        acc += __cosf(p.y * q.y);
        acc += __cosf(p.z * q.z);
        acc += __cosf(p.w * q.w);
    }
    // scalar tail (n % 4)
    int done = n4 << 2;
    if (gtid < n - done) {
        int idx = done + gtid;
        acc += __cosf(phi[idx] * w[idx]);
    }

    // block reduce
    #pragma unroll
    for (int off = 16; off > 0; off >>= 1)
        acc += __shfl_down_sync(0xFFFFFFFFu, acc, off);

    __shared__ float s_warp[THREADS / 32];
    int lane = tid & 31;
    int wid  = tid >> 5;
    if (lane == 0) s_warp[wid] = acc;
    __syncthreads();

    __shared__ bool s_last;
    if (tid == 0) {
        float v = 0.0f;
        #pragma unroll
        for (int k = 0; k < THREADS / 32; k++) v += s_warp[k];
        g_partials[blockIdx.x] = v;
        __threadfence();
        unsigned int t = atomicInc(&g_ticket, (unsigned int)(gridDim.x - 1));
        s_last = (t == (unsigned int)(gridDim.x - 1));
    }
    __syncthreads();

    if (s_last) {
        // deterministic fixed-order reduction of block partials in double
        __shared__ double s_red[THREADS / 32];
        double v = 0.0;
        for (int k = tid; k < (int)gridDim.x; k += THREADS)
            v += (double)g_partials[k];
        #pragma unroll
        for (int off = 16; off > 0; off >>= 1)
            v += __shfl_down_sync(0xFFFFFFFFu, v, off);
        if (lane == 0) s_red[wid] = v;
        __syncthreads();
        if (wid == 0) {
            double x = (lane < THREADS / 32) ? s_red[lane] : 0.0;
            #pragma unroll
            for (int off = 4; off > 0; off >>= 1)
                x += __shfl_down_sync(0xFFFFFFFFu, x, off);
            if (lane == 0)
                out[0] = (float)((x + (double)add_const) * (double)inv_m);
        }
    }
}

extern "C" void kernel_launch(void* const* d_in, const int* in_sizes, int n_in,
                              void* d_out, int out_size)
{
    const float* phi = (const float*)d_in[0];
    const float* w   = (const float*)d_in[1];
    float* out = (float*)d_out;
    int n = in_sizes[0];

    long long M = 1;
    while (M < (long long)n) M <<= 1;
    float add_const = (float)(M - (long long)n);
    float inv_m = (float)(1.0 / (double)M);

    qsum_cpasync_kernel<<<NBLOCKS, THREADS>>>(phi, w, n, add_const, inv_m, out);
}

// round 11
// speedup vs baseline: 1.0713x; 1.0666x over previous
#include <cuda_runtime.h>
#include <cuda_bf16.h>

#define RED_BLOCKS 1184          // 148 SMs * 8
#define RED_THREADS 256

__device__ float g_partials[RED_BLOCKS];
__device__ unsigned int g_ticket;   // zero-initialized; atomicInc wraps back to 0

__global__ void __launch_bounds__(RED_THREADS, 8)
qsum_fused_kernel(const float* __restrict__ phi,
                  const float* __restrict__ w,
                  int n, int nblocks,
                  float add_const, float inv_m,
                  float* __restrict__ out)
{
    const int n8 = n >> 3;                       // 32-byte chunks per array
    const float4* __restrict__ p4 = reinterpret_cast<const float4*>(phi);
    const float4* __restrict__ w4 = reinterpret_cast<const float4*>(w);

    const int stride = gridDim.x * blockDim.x;
    float acc = 0.0f;

    // each iteration: 32 contiguous bytes from each array (2 adjacent float4),
    // streaming (evict-first) loads — best measured variant (5.24 TB/s)
    for (int i = blockIdx.x * blockDim.x + threadIdx.x; i < n8; i += stride) {
        float4 pa = __ldcs(p4 + 2 * i);
        float4 qa = __ldcs(w4 + 2 * i);
        float4 pb = __ldcs(p4 + 2 * i + 1);
        float4 qb = __ldcs(w4 + 2 * i + 1);
        acc += __cosf(pa.x * qa.x);
        acc += __cosf(pa.y * qa.y);
        acc += __cosf(pa.z * qa.z);
        acc += __cosf(pa.w * qa.w);
        acc += __cosf(pb.x * qb.x);
        acc += __cosf(pb.y * qb.y);
        acc += __cosf(pb.z * qb.z);
        acc += __cosf(pb.w * qb.w);
    }

    // scalar tail (n % 8 elements)
    int done = n8 << 3;
    int tail = n - done;
    int gtid = blockIdx.x * blockDim.x + threadIdx.x;
    if (gtid < tail) {
        int idx = done + gtid;
        acc += __cosf(phi[idx] * w[idx]);
    }

    // warp reduce
    #pragma unroll
    for (int off = 16; off > 0; off >>= 1)
        acc += __shfl_down_sync(0xFFFFFFFFu, acc, off);

    __shared__ float s_warp[RED_THREADS / 32];
    int lane = threadIdx.x & 31;
    int wid  = threadIdx.x >> 5;
    if (lane == 0) s_warp[wid] = acc;
    __syncthreads();

    __shared__ bool s_last;
    if (threadIdx.x == 0) {
        float v = 0.0f;
        #pragma unroll
        for (int k = 0; k < RED_THREADS / 32; k++) v += s_warp[k];
        g_partials[blockIdx.x] = v;
        __threadfence();
        // atomicInc wraps to 0 when old == nblocks-1 -> counter self-resets
        unsigned int t = atomicInc(&g_ticket, (unsigned int)(nblocks - 1));
        s_last = (t == (unsigned int)(nblocks - 1));
    }
    __syncthreads();

    if (s_last) {
        // last block: deterministic fixed-order reduction of partials in double
        __shared__ double s_red[RED_THREADS / 32];
        double v = 0.0;
        for (int k = threadIdx.x; k < nblocks; k += RED_THREADS)
            v += (double)g_partials[k];
        #pragma unroll
        for (int off = 16; off > 0; off >>= 1)
            v += __shfl_down_sync(0xFFFFFFFFu, v, off);
        if (lane == 0) s_red[wid] = v;
        __syncthreads();
        if (wid == 0) {
            double x = (lane < RED_THREADS / 32) ? s_red[lane] : 0.0;
            #pragma unroll
            for (int off = 4; off > 0; off >>= 1)
                x += __shfl_down_sync(0xFFFFFFFFu, x, off);
            if (lane == 0)
                out[0] = (float)((x + (double)add_const) * (double)inv_m);
        }
    }
}

extern "C" void kernel_launch(void* const* d_in, const int* in_sizes, int n_in,
                              void* d_out, int out_size)
{
    const float* phi = (const float*)d_in[0];
    const float* w   = (const float*)d_in[1];
    float* out = (float*)d_out;
    int n = in_sizes[0];

    long long M = 1;
    while (M < (long long)n) M <<= 1;
    float add_const = (float)(M - (long long)n);
    float inv_m = (float)(1.0 / (double)M);

    int blocks = RED_BLOCKS;
    long long work8 = (n >> 3);
    if (work8 < (long long)blocks * RED_THREADS) {
        blocks = (int)((work8 + RED_THREADS - 1) / RED_THREADS);
        if (blocks < 1) blocks = 1;
    }

    qsum_fused_kernel<<<blocks, RED_THREADS>>>(phi, w, n, blocks,
                                               add_const, inv_m, out);
}